// round 2
// baseline (speedup 1.0000x reference)
#include <cuda_runtime.h>
#include <math.h>

// Problem constants
#define D_DIM 1536
#define E_NUM 64
#define H_DIM 384
#define TOPK  8
#define CAP   1024
#define T_NUM 4096

// ---------------- scratch (static device globals; no allocations) ----------
__device__ __align__(16) int   g_counts[E_NUM];
__device__ __align__(16) int   g_slot_token[E_NUM * CAP];
__device__ __align__(16) float g_slot_weight[E_NUM * CAP];
__device__ __align__(16) float g_act[(size_t)E_NUM * CAP * H_DIM]; // ~100 MB

// ---------------- kernel 1: zero out + counters ----------------------------
__global__ void zero_kernel(float* __restrict__ out) {
    int i = blockIdx.x * blockDim.x + threadIdx.x;
    if (blockIdx.x == 0 && threadIdx.x < E_NUM) g_counts[threadIdx.x] = 0;
    const int n4 = T_NUM * D_DIM / 4;
    float4 z = make_float4(0.f, 0.f, 0.f, 0.f);
    for (int idx = i; idx < n4; idx += gridDim.x * blockDim.x)
        ((float4*)out)[idx] = z;
}

// ---------------- kernel 2: router (logits + softmax + top8 + dispatch) ----
// 8 tokens per block, 256 threads. Dynamic smem: xs[8][D] + logits[8][64].
extern __shared__ float s_router[];

__global__ __launch_bounds__(256) void router_kernel(
    const float* __restrict__ x, const float* __restrict__ gate_w)
{
    float (*xs)[D_DIM] = (float (*)[D_DIM])s_router;
    float (*lg)[E_NUM] = (float (*)[E_NUM])(s_router + 8 * D_DIM);

    const int tid = threadIdx.x;
    const int t0 = blockIdx.x * 8;

    // cooperative load of 8 token rows
    const float4* xg = (const float4*)(x + (size_t)t0 * D_DIM);
    float4* xs4 = (float4*)xs;
    for (int i = tid; i < 8 * D_DIM / 4; i += 256) xs4[i] = xg[i];
    __syncthreads();

    const int warp = tid >> 5, lane = tid & 31;

    // each warp computes 8 experts for all 8 tokens
    for (int j = 0; j < 8; j++) {
        const int e = warp * 8 + j;
        const float4* gr = (const float4*)(gate_w + (size_t)e * D_DIM);
        float acc[8];
#pragma unroll
        for (int t = 0; t < 8; t++) acc[t] = 0.f;
        for (int d4 = lane; d4 < D_DIM / 4; d4 += 32) {
            float4 g = gr[d4];
#pragma unroll
            for (int t = 0; t < 8; t++) {
                float4 xv = *(const float4*)(&xs[t][d4 * 4]);
                acc[t] = fmaf(g.x, xv.x, fmaf(g.y, xv.y,
                          fmaf(g.z, xv.z, fmaf(g.w, xv.w, acc[t]))));
            }
        }
#pragma unroll
        for (int off = 16; off > 0; off >>= 1)
#pragma unroll
            for (int t = 0; t < 8; t++)
                acc[t] += __shfl_xor_sync(0xffffffffu, acc[t], off);
        if (lane == 0)
#pragma unroll
            for (int t = 0; t < 8; t++) lg[t][e] = acc[t];
    }
    __syncthreads();

    // warp w handles token w: softmax (fp32), top-8 (lower index wins ties), renorm
    {
        const int t = warp;
        float v0 = lg[t][lane];
        float v1 = lg[t][lane + 32];
        float m = fmaxf(v0, v1);
#pragma unroll
        for (int off = 16; off > 0; off >>= 1)
            m = fmaxf(m, __shfl_xor_sync(0xffffffffu, m, off));
        float e0 = expf(v0 - m), e1 = expf(v1 - m);
        float s = e0 + e1;
#pragma unroll
        for (int off = 16; off > 0; off >>= 1)
            s += __shfl_xor_sync(0xffffffffu, s, off);
        float p0 = e0 / s, p1 = e1 / s;

        float selw[TOPK];
        int   sele[TOPK];
#pragma unroll
        for (int k = 0; k < TOPK; k++) {
            float bv; int bi;
            if (p0 >= p1) { bv = p0; bi = lane; }
            else          { bv = p1; bi = lane + 32; }
#pragma unroll
            for (int off = 16; off > 0; off >>= 1) {
                float ov = __shfl_xor_sync(0xffffffffu, bv, off);
                int   oi = __shfl_xor_sync(0xffffffffu, bi, off);
                if (ov > bv || (ov == bv && oi < bi)) { bv = ov; bi = oi; }
            }
            selw[k] = bv; sele[k] = bi;
            if (bi == lane)      p0 = -1.f;
            if (bi == lane + 32) p1 = -1.f;
        }
        float wsum = 0.f;
#pragma unroll
        for (int k = 0; k < TOPK; k++) wsum += selw[k];

        if (lane == 0) {
            const int tok = t0 + t;
#pragma unroll
            for (int k = 0; k < TOPK; k++) {
                const int e = sele[k];
                const int pos = atomicAdd(&g_counts[e], 1);
                if (pos < CAP) {
                    g_slot_token[e * CAP + pos]  = tok;
                    g_slot_weight[e * CAP + pos] = selw[k] / wsum;
                }
            }
        }
    }
}

// ---------------- kernel 3: grouped GEMM1 (gate+up fused, SwiGLU) ----------
// BM=64, BN=64 (over H), BK=16; 256 threads; 4x4 microtile; dual accumulators.
__global__ __launch_bounds__(256) void gemm1_kernel(
    const float* __restrict__ x,
    const float* __restrict__ Wg,   // [E, D, H]
    const float* __restrict__ Wu)   // [E, D, H]
{
    const int e = blockIdx.z;
    const int n_e = min(g_counts[e], CAP);
    const int row0 = blockIdx.y * 64;
    if (row0 >= n_e) return;
    const int col0 = blockIdx.x * 64;

    __shared__ float Xs[16][68];
    __shared__ float Gs[16][68];
    __shared__ float Us[16][68];
    __shared__ int   stok[64];

    const int tid = threadIdx.x;
    if (tid < 64) {
        const int r = row0 + tid;
        stok[tid] = (r < n_e) ? g_slot_token[e * CAP + r] : -1;
    }
    __syncthreads();

    const int ty = tid >> 4, tx = tid & 15;
    float accg[4][4] = {}, accu[4][4] = {};

    // X load mapping: one float4 per thread
    const int lr = tid >> 2;            // 0..63 (local row)
    const int lc = (tid & 3) * 4;       // 0,4,8,12 (k offset)
    const int tokr = stok[lr];
    const float* xrow = (tokr >= 0) ? (x + (size_t)tokr * D_DIM) : x;
    const bool xok = (tokr >= 0);

    // W load mapping: one float4 per thread per matrix
    const int wk = tid >> 4;            // 0..15 (k)
    const int wn = (tid & 15) * 4;      // 0..60 (n)
    const float* wg_base = Wg + (size_t)e * D_DIM * H_DIM + col0 + wn;
    const float* wu_base = Wu + (size_t)e * D_DIM * H_DIM + col0 + wn;

    for (int kk = 0; kk < D_DIM; kk += 16) {
        float4 xv = make_float4(0.f, 0.f, 0.f, 0.f);
        if (xok) xv = *(const float4*)(xrow + kk + lc);
        float4 gv = *(const float4*)(wg_base + (size_t)(kk + wk) * H_DIM);
        float4 uv = *(const float4*)(wu_base + (size_t)(kk + wk) * H_DIM);

        __syncthreads();
        Xs[lc + 0][lr] = xv.x; Xs[lc + 1][lr] = xv.y;
        Xs[lc + 2][lr] = xv.z; Xs[lc + 3][lr] = xv.w;
        *(float4*)&Gs[wk][wn] = gv;
        *(float4*)&Us[wk][wn] = uv;
        __syncthreads();

#pragma unroll
        for (int k = 0; k < 16; k++) {
            float4 a  = *(const float4*)&Xs[k][ty * 4];
            float4 bg = *(const float4*)&Gs[k][tx * 4];
            float4 bu = *(const float4*)&Us[k][tx * 4];
            float av[4]  = {a.x, a.y, a.z, a.w};
            float bgv[4] = {bg.x, bg.y, bg.z, bg.w};
            float buv[4] = {bu.x, bu.y, bu.z, bu.w};
#pragma unroll
            for (int i = 0; i < 4; i++)
#pragma unroll
                for (int j = 0; j < 4; j++) {
                    accg[i][j] = fmaf(av[i], bgv[j], accg[i][j]);
                    accu[i][j] = fmaf(av[i], buv[j], accu[i][j]);
                }
        }
    }

    // epilogue: SwiGLU, store to act scratch
#pragma unroll
    for (int i = 0; i < 4; i++) {
        const int r = row0 + ty * 4 + i;
        if (r >= n_e) continue;
        float* arow = g_act + ((size_t)e * CAP + r) * H_DIM + col0 + tx * 4;
        float4 o;
        float g, u;
        g = accg[i][0]; u = accu[i][0]; o.x = (g / (1.f + expf(-g))) * u;
        g = accg[i][1]; u = accu[i][1]; o.y = (g / (1.f + expf(-g))) * u;
        g = accg[i][2]; u = accu[i][2]; o.z = (g / (1.f + expf(-g))) * u;
        g = accg[i][3]; u = accu[i][3]; o.w = (g / (1.f + expf(-g))) * u;
        *(float4*)arow = o;
    }
}

// ---------------- kernel 4: grouped GEMM2 (down proj) + weighted scatter ---
// BM=64, BN=128 (over D), BK=16; 256 threads; 4x8 microtile; atomicAdd combine.
__global__ __launch_bounds__(256) void gemm2_kernel(
    const float* __restrict__ Wd,   // [E, H, D]
    float* __restrict__ out)
{
    const int e = blockIdx.z;
    const int n_e = min(g_counts[e], CAP);
    const int row0 = blockIdx.y * 64;
    if (row0 >= n_e) return;
    const int col0 = blockIdx.x * 128;

    __shared__ float As[16][68];
    __shared__ float Bs[16][132];
    __shared__ int   stok[64];
    __shared__ float sw[64];

    const int tid = threadIdx.x;
    if (tid < 64) {
        const int r = row0 + tid;
        stok[tid] = (r < n_e) ? g_slot_token[e * CAP + r] : 0;
        sw[tid]   = (r < n_e) ? g_slot_weight[e * CAP + r] : 0.f;
    }

    const int ty = tid >> 4, tx = tid & 15;
    float acc[4][8] = {};

    const int lr = tid >> 2;
    const int lc = (tid & 3) * 4;
    const bool arow_ok = (row0 + lr) < n_e;
    const float* arow = g_act + ((size_t)e * CAP + row0 + lr) * H_DIM;
    const float* wd_base = Wd + (size_t)e * H_DIM * D_DIM + col0;

    for (int kk = 0; kk < H_DIM; kk += 16) {
        float4 av = make_float4(0.f, 0.f, 0.f, 0.f);
        if (arow_ok) av = *(const float4*)(arow + kk + lc);
        float4 bvv[2];
#pragma unroll
        for (int it = 0; it < 2; it++) {
            const int idx = tid + it * 256;   // 0..511
            const int bk = idx >> 5;          // 0..15
            const int bn = (idx & 31) * 4;    // 0..124
            bvv[it] = *(const float4*)(wd_base + (size_t)(kk + bk) * D_DIM + bn);
        }

        __syncthreads();
        As[lc + 0][lr] = av.x; As[lc + 1][lr] = av.y;
        As[lc + 2][lr] = av.z; As[lc + 3][lr] = av.w;
#pragma unroll
        for (int it = 0; it < 2; it++) {
            const int idx = tid + it * 256;
            const int bk = idx >> 5;
            const int bn = (idx & 31) * 4;
            *(float4*)&Bs[bk][bn] = bvv[it];
        }
        __syncthreads();

#pragma unroll
        for (int k = 0; k < 16; k++) {
            float4 a  = *(const float4*)&As[k][ty * 4];
            float4 b0 = *(const float4*)&Bs[k][tx * 8];
            float4 b1 = *(const float4*)&Bs[k][tx * 8 + 4];
            float avr[4] = {a.x, a.y, a.z, a.w};
            float bvr[8] = {b0.x, b0.y, b0.z, b0.w, b1.x, b1.y, b1.z, b1.w};
#pragma unroll
            for (int i = 0; i < 4; i++)
#pragma unroll
                for (int j = 0; j < 8; j++)
                    acc[i][j] = fmaf(avr[i], bvr[j], acc[i][j]);
        }
    }

    // epilogue: weighted scatter-add into out
#pragma unroll
    for (int i = 0; i < 4; i++) {
        const int r = row0 + ty * 4 + i;
        if (r >= n_e) continue;
        const int t = stok[ty * 4 + i];
        const float w = sw[ty * 4 + i];
        float* orow = out + (size_t)t * D_DIM + col0 + tx * 8;
#pragma unroll
        for (int j = 0; j < 8; j++)
            atomicAdd(&orow[j], w * acc[i][j]);
    }
}

// ---------------- launcher --------------------------------------------------
extern "C" void kernel_launch(void* const* d_in, const int* in_sizes, int n_in,
                              void* d_out, int out_size)
{
    const float* x      = (const float*)d_in[0];
    const float* gate_w = (const float*)d_in[1];
    const float* W_gate = (const float*)d_in[2];
    const float* W_up   = (const float*)d_in[3];
    const float* W_down = (const float*)d_in[4];
    float* out = (float*)d_out;

    const int router_smem = 8 * D_DIM * 4 + 8 * E_NUM * 4;  // 51200 bytes
    cudaFuncSetAttribute(router_kernel,
                         cudaFuncAttributeMaxDynamicSharedMemorySize,
                         router_smem);

    zero_kernel<<<1024, 256>>>(out);
    router_kernel<<<T_NUM / 8, 256, router_smem>>>(x, gate_w);
    gemm1_kernel<<<dim3(H_DIM / 64, CAP / 64, E_NUM), 256>>>(x, W_gate, W_up);
    gemm2_kernel<<<dim3(D_DIM / 128, CAP / 64, E_NUM), 256>>>(W_down, out);
}

// round 4
// speedup vs baseline: 2.5985x; 2.5985x over previous
#include <cuda_runtime.h>
#include <math.h>
#include <stdint.h>

#define D_DIM 1536
#define E_NUM 64
#define H_DIM 384
#define TOPK  8
#define CAP   1024
#define T_NUM 4096
#define SA    20   // smem row stride (uint32 units): conflict-free for 1688 frags

// ---------------- scratch (static device globals; no allocations) ----------
__device__ __align__(16) int   g_counts[E_NUM];
__device__ __align__(16) int   g_slot_token[E_NUM * CAP];
__device__ __align__(16) float g_slot_weight[E_NUM * CAP];
__device__ __align__(16) int   g_tok_slot[T_NUM * TOPK];
__device__ __align__(16) float g_act[(size_t)E_NUM * CAP * H_DIM];  // ~100 MB
__device__ __align__(16) float g_y[(size_t)E_NUM * CAP * D_DIM];    // ~402 MB

// ---------------- helpers ----------------------------------------------------
__device__ __forceinline__ uint32_t tf32_rna(float x) {
    uint32_t r; asm("cvt.rna.tf32.f32 %0, %1;" : "=r"(r) : "f"(x)); return r;
}
__device__ __forceinline__ void mma1688(float c[4],
                                        uint32_t a0, uint32_t a1, uint32_t a2, uint32_t a3,
                                        uint32_t b0, uint32_t b1) {
    asm volatile(
        "mma.sync.aligned.m16n8k8.row.col.f32.tf32.tf32.f32 "
        "{%0,%1,%2,%3}, {%4,%5,%6,%7}, {%8,%9}, {%0,%1,%2,%3};"
        : "+f"(c[0]), "+f"(c[1]), "+f"(c[2]), "+f"(c[3])
        : "r"(a0), "r"(a1), "r"(a2), "r"(a3), "r"(b0), "r"(b1));
}
__device__ __forceinline__ float silu(float g) { return g / (1.f + expf(-g)); }

// ---------------- kernel 0: init counters -----------------------------------
__global__ void init_kernel() {
    if (threadIdx.x < E_NUM) g_counts[threadIdx.x] = 0;
}

// ---------------- kernel 1: router ------------------------------------------
extern __shared__ float s_dyn[];

__global__ __launch_bounds__(256) void router_kernel(
    const float* __restrict__ x, const float* __restrict__ gate_w)
{
    float (*xs)[D_DIM] = (float (*)[D_DIM])s_dyn;
    float (*lg)[E_NUM] = (float (*)[E_NUM])(s_dyn + 8 * D_DIM);

    const int tid = threadIdx.x;
    const int t0 = blockIdx.x * 8;

    const float4* xg = (const float4*)(x + (size_t)t0 * D_DIM);
    float4* xs4 = (float4*)xs;
    for (int i = tid; i < 8 * D_DIM / 4; i += 256) xs4[i] = xg[i];
    __syncthreads();

    const int warp = tid >> 5, lane = tid & 31;

    for (int j = 0; j < 8; j++) {
        const int e = warp * 8 + j;
        const float4* gr = (const float4*)(gate_w + (size_t)e * D_DIM);
        float acc[8];
#pragma unroll
        for (int t = 0; t < 8; t++) acc[t] = 0.f;
        for (int d4 = lane; d4 < D_DIM / 4; d4 += 32) {
            float4 g = gr[d4];
#pragma unroll
            for (int t = 0; t < 8; t++) {
                float4 xv = *(const float4*)(&xs[t][d4 * 4]);
                acc[t] = fmaf(g.x, xv.x, fmaf(g.y, xv.y,
                          fmaf(g.z, xv.z, fmaf(g.w, xv.w, acc[t]))));
            }
        }
#pragma unroll
        for (int off = 16; off > 0; off >>= 1)
#pragma unroll
            for (int t = 0; t < 8; t++)
                acc[t] += __shfl_xor_sync(0xffffffffu, acc[t], off);
        if (lane == 0)
#pragma unroll
            for (int t = 0; t < 8; t++) lg[t][e] = acc[t];
    }
    __syncthreads();

    {
        const int t = warp;
        float v0 = lg[t][lane];
        float v1 = lg[t][lane + 32];
        float m = fmaxf(v0, v1);
#pragma unroll
        for (int off = 16; off > 0; off >>= 1)
            m = fmaxf(m, __shfl_xor_sync(0xffffffffu, m, off));
        float e0 = expf(v0 - m), e1 = expf(v1 - m);
        float s = e0 + e1;
#pragma unroll
        for (int off = 16; off > 0; off >>= 1)
            s += __shfl_xor_sync(0xffffffffu, s, off);
        float p0 = e0 / s, p1 = e1 / s;

        float selw[TOPK];
        int   sele[TOPK];
#pragma unroll
        for (int k = 0; k < TOPK; k++) {
            float bv; int bi;
            if (p0 >= p1) { bv = p0; bi = lane; }
            else          { bv = p1; bi = lane + 32; }
#pragma unroll
            for (int off = 16; off > 0; off >>= 1) {
                float ov = __shfl_xor_sync(0xffffffffu, bv, off);
                int   oi = __shfl_xor_sync(0xffffffffu, bi, off);
                if (ov > bv || (ov == bv && oi < bi)) { bv = ov; bi = oi; }
            }
            selw[k] = bv; sele[k] = bi;
            if (bi == lane)      p0 = -1.f;
            if (bi == lane + 32) p1 = -1.f;
        }
        float wsum = 0.f;
#pragma unroll
        for (int k = 0; k < TOPK; k++) wsum += selw[k];

        if (lane == 0) {
            const int tok = t0 + t;
#pragma unroll
            for (int k = 0; k < TOPK; k++) {
                const int e = sele[k];
                const int pos = atomicAdd(&g_counts[e], 1);
                if (pos < CAP) {
                    g_slot_token[e * CAP + pos]  = tok;
                    g_slot_weight[e * CAP + pos] = selw[k] / wsum;
                    g_tok_slot[tok * TOPK + k]   = e * CAP + pos;
                } else {
                    g_tok_slot[tok * TOPK + k]   = -1;
                }
            }
        }
    }
}

// ---------------- kernel 2: grouped GEMM1 (mma.sync tf32, SwiGLU) -----------
// CTA 128(M) x 64(H), BK=16, 8 warps (4M x 2N), warp 32x32, dual acc (gate,up)
__global__ __launch_bounds__(256) void gemm1_kernel(
    const float* __restrict__ x,
    const float* __restrict__ Wg,
    const float* __restrict__ Wu)
{
    const int e = blockIdx.z;
    const int n_e = min(g_counts[e], CAP);
    const int row0 = blockIdx.x * 128;
    if (row0 >= n_e) return;
    const int col0 = blockIdx.y * 64;

    __shared__ uint32_t As[2][128 * SA];
    __shared__ uint32_t Bgs[2][64 * SA];
    __shared__ uint32_t Bus[2][64 * SA];
    __shared__ int stok[128];

    const int tid = threadIdx.x;
    if (tid < 128) {
        const int r = row0 + tid;
        stok[tid] = (r < n_e) ? g_slot_token[e * CAP + r] : 0;
    }
    __syncthreads();

    const float* wg_e = Wg + (size_t)e * D_DIM * H_DIM + col0;
    const float* wu_e = Wu + (size_t)e * D_DIM * H_DIM + col0;

    // load mappings
    const int ar = tid >> 2, ac4 = tid & 3;          // A: rows ar, ar+64; k-quad ac4
    const int bn = tid & 63, bk4 = tid >> 6;         // B: n, k-quad

    const float* xr0 = x + (size_t)stok[ar] * D_DIM + ac4 * 4;
    const float* xr1 = x + (size_t)stok[ar + 64] * D_DIM + ac4 * 4;

    const int lane = tid & 31, wid = tid >> 5;
    const int g = lane >> 2, t = lane & 3;
    const int m0 = (wid >> 1) * 32, n0 = (wid & 1) * 32;

    float accg[2][4][4] = {}, accu[2][4][4] = {};

    const int NCH = D_DIM / 16;  // 96

    // prologue: load chunk 0
    {
        float4 v0 = *(const float4*)(xr0);
        float4 v1 = *(const float4*)(xr1);
        *(uint4*)&As[0][ar * SA + ac4 * 4] =
            make_uint4(tf32_rna(v0.x), tf32_rna(v0.y), tf32_rna(v0.z), tf32_rna(v0.w));
        *(uint4*)&As[0][(ar + 64) * SA + ac4 * 4] =
            make_uint4(tf32_rna(v1.x), tf32_rna(v1.y), tf32_rna(v1.z), tf32_rna(v1.w));
        const float* pg = wg_e + (size_t)(bk4 * 4) * H_DIM + bn;
        const float* pu = wu_e + (size_t)(bk4 * 4) * H_DIM + bn;
        *(uint4*)&Bgs[0][bn * SA + bk4 * 4] =
            make_uint4(tf32_rna(pg[0]), tf32_rna(pg[H_DIM]),
                       tf32_rna(pg[2 * H_DIM]), tf32_rna(pg[3 * H_DIM]));
        *(uint4*)&Bus[0][bn * SA + bk4 * 4] =
            make_uint4(tf32_rna(pu[0]), tf32_rna(pu[H_DIM]),
                       tf32_rna(pu[2 * H_DIM]), tf32_rna(pu[3 * H_DIM]));
    }
    __syncthreads();

    int buf = 0;
    for (int c = 0; c < NCH; c++) {
        // prefetch chunk c+1 into registers
        float4 v0, v1; uint4 gq, uq;
        const bool pre = (c + 1 < NCH);
        if (pre) {
            const int kk = (c + 1) * 16;
            v0 = *(const float4*)(xr0 + kk);
            v1 = *(const float4*)(xr1 + kk);
            const float* pg = wg_e + (size_t)(kk + bk4 * 4) * H_DIM + bn;
            const float* pu = wu_e + (size_t)(kk + bk4 * 4) * H_DIM + bn;
            gq = make_uint4(tf32_rna(pg[0]), tf32_rna(pg[H_DIM]),
                            tf32_rna(pg[2 * H_DIM]), tf32_rna(pg[3 * H_DIM]));
            uq = make_uint4(tf32_rna(pu[0]), tf32_rna(pu[H_DIM]),
                            tf32_rna(pu[2 * H_DIM]), tf32_rna(pu[3 * H_DIM]));
        }

        // compute on buf
#pragma unroll
        for (int ks = 0; ks < 2; ks++) {
            const int kc = ks * 8;
            uint32_t a[2][4];
#pragma unroll
            for (int mf = 0; mf < 2; mf++) {
                const int r = m0 + mf * 16 + g;
                a[mf][0] = As[buf][r * SA + kc + t];
                a[mf][1] = As[buf][(r + 8) * SA + kc + t];
                a[mf][2] = As[buf][r * SA + kc + t + 4];
                a[mf][3] = As[buf][(r + 8) * SA + kc + t + 4];
            }
            uint32_t bg[4][2], bu[4][2];
#pragma unroll
            for (int nf = 0; nf < 4; nf++) {
                const int n = n0 + nf * 8 + g;
                bg[nf][0] = Bgs[buf][n * SA + kc + t];
                bg[nf][1] = Bgs[buf][n * SA + kc + t + 4];
                bu[nf][0] = Bus[buf][n * SA + kc + t];
                bu[nf][1] = Bus[buf][n * SA + kc + t + 4];
            }
#pragma unroll
            for (int mf = 0; mf < 2; mf++)
#pragma unroll
                for (int nf = 0; nf < 4; nf++) {
                    mma1688(accg[mf][nf], a[mf][0], a[mf][1], a[mf][2], a[mf][3],
                            bg[nf][0], bg[nf][1]);
                    mma1688(accu[mf][nf], a[mf][0], a[mf][1], a[mf][2], a[mf][3],
                            bu[nf][0], bu[nf][1]);
                }
        }

        if (pre) {
            const int nb = buf ^ 1;
            *(uint4*)&As[nb][ar * SA + ac4 * 4] =
                make_uint4(tf32_rna(v0.x), tf32_rna(v0.y), tf32_rna(v0.z), tf32_rna(v0.w));
            *(uint4*)&As[nb][(ar + 64) * SA + ac4 * 4] =
                make_uint4(tf32_rna(v1.x), tf32_rna(v1.y), tf32_rna(v1.z), tf32_rna(v1.w));
            *(uint4*)&Bgs[nb][bn * SA + bk4 * 4] = gq;
            *(uint4*)&Bus[nb][bn * SA + bk4 * 4] = uq;
        }
        __syncthreads();
        buf ^= 1;
    }

    // epilogue: SwiGLU -> g_act
#pragma unroll
    for (int mf = 0; mf < 2; mf++) {
        const int rbase = row0 + m0 + mf * 16 + g;
#pragma unroll
        for (int nf = 0; nf < 4; nf++) {
            const int col = col0 + n0 + nf * 8 + 2 * t;
            if (rbase < n_e) {
                float2 o;
                o.x = silu(accg[mf][nf][0]) * accu[mf][nf][0];
                o.y = silu(accg[mf][nf][1]) * accu[mf][nf][1];
                *(float2*)(g_act + ((size_t)e * CAP + rbase) * H_DIM + col) = o;
            }
            if (rbase + 8 < n_e) {
                float2 o;
                o.x = silu(accg[mf][nf][2]) * accu[mf][nf][2];
                o.y = silu(accg[mf][nf][3]) * accu[mf][nf][3];
                *(float2*)(g_act + ((size_t)e * CAP + rbase + 8) * H_DIM + col) = o;
            }
        }
    }
}

// ---------------- kernel 3: grouped GEMM2 (mma.sync tf32, weighted y) -------
// CTA 128(M) x 64(D), BK=16, warp 32x32
__global__ __launch_bounds__(256) void gemm2_kernel(const float* __restrict__ Wd)
{
    const int e = blockIdx.z;
    const int n_e = min(g_counts[e], CAP);
    const int row0 = blockIdx.x * 128;
    if (row0 >= n_e) return;
    const int col0 = blockIdx.y * 64;

    __shared__ uint32_t As[2][128 * SA];
    __shared__ uint32_t Bs[2][64 * SA];
    __shared__ float sw[128];

    const int tid = threadIdx.x;
    if (tid < 128) {
        const int r = row0 + tid;
        sw[tid] = (r < n_e) ? g_slot_weight[e * CAP + r] : 0.f;
    }
    __syncthreads();

    const float* wd_e = Wd + (size_t)e * H_DIM * D_DIM + col0;

    const int ar = tid >> 2, ac4 = tid & 3;
    const int bn = tid & 63, bk4 = tid >> 6;

    const float* ar0 = g_act + ((size_t)e * CAP + row0 + ar) * H_DIM + ac4 * 4;
    const float* ar1 = g_act + ((size_t)e * CAP + row0 + ar + 64) * H_DIM + ac4 * 4;

    const int lane = tid & 31, wid = tid >> 5;
    const int g = lane >> 2, t = lane & 3;
    const int m0 = (wid >> 1) * 32, n0 = (wid & 1) * 32;

    float acc[2][4][4] = {};

    const int NCH = H_DIM / 16;  // 24

    {
        float4 v0 = *(const float4*)(ar0);
        float4 v1 = *(const float4*)(ar1);
        *(uint4*)&As[0][ar * SA + ac4 * 4] =
            make_uint4(tf32_rna(v0.x), tf32_rna(v0.y), tf32_rna(v0.z), tf32_rna(v0.w));
        *(uint4*)&As[0][(ar + 64) * SA + ac4 * 4] =
            make_uint4(tf32_rna(v1.x), tf32_rna(v1.y), tf32_rna(v1.z), tf32_rna(v1.w));
        const float* pb = wd_e + (size_t)(bk4 * 4) * D_DIM + bn;
        *(uint4*)&Bs[0][bn * SA + bk4 * 4] =
            make_uint4(tf32_rna(pb[0]), tf32_rna(pb[D_DIM]),
                       tf32_rna(pb[2 * D_DIM]), tf32_rna(pb[3 * D_DIM]));
    }
    __syncthreads();

    int buf = 0;
    for (int c = 0; c < NCH; c++) {
        float4 v0, v1; uint4 bq;
        const bool pre = (c + 1 < NCH);
        if (pre) {
            const int kk = (c + 1) * 16;
            v0 = *(const float4*)(ar0 + kk);
            v1 = *(const float4*)(ar1 + kk);
            const float* pb = wd_e + (size_t)(kk + bk4 * 4) * D_DIM + bn;
            bq = make_uint4(tf32_rna(pb[0]), tf32_rna(pb[D_DIM]),
                            tf32_rna(pb[2 * D_DIM]), tf32_rna(pb[3 * D_DIM]));
        }

#pragma unroll
        for (int ks = 0; ks < 2; ks++) {
            const int kc = ks * 8;
            uint32_t a[2][4];
#pragma unroll
            for (int mf = 0; mf < 2; mf++) {
                const int r = m0 + mf * 16 + g;
                a[mf][0] = As[buf][r * SA + kc + t];
                a[mf][1] = As[buf][(r + 8) * SA + kc + t];
                a[mf][2] = As[buf][r * SA + kc + t + 4];
                a[mf][3] = As[buf][(r + 8) * SA + kc + t + 4];
            }
            uint32_t bb[4][2];
#pragma unroll
            for (int nf = 0; nf < 4; nf++) {
                const int n = n0 + nf * 8 + g;
                bb[nf][0] = Bs[buf][n * SA + kc + t];
                bb[nf][1] = Bs[buf][n * SA + kc + t + 4];
            }
#pragma unroll
            for (int mf = 0; mf < 2; mf++)
#pragma unroll
                for (int nf = 0; nf < 4; nf++)
                    mma1688(acc[mf][nf], a[mf][0], a[mf][1], a[mf][2], a[mf][3],
                            bb[nf][0], bb[nf][1]);
        }

        if (pre) {
            const int nb = buf ^ 1;
            *(uint4*)&As[nb][ar * SA + ac4 * 4] =
                make_uint4(tf32_rna(v0.x), tf32_rna(v0.y), tf32_rna(v0.z), tf32_rna(v0.w));
            *(uint4*)&As[nb][(ar + 64) * SA + ac4 * 4] =
                make_uint4(tf32_rna(v1.x), tf32_rna(v1.y), tf32_rna(v1.z), tf32_rna(v1.w));
            *(uint4*)&Bs[nb][bn * SA + bk4 * 4] = bq;
        }
        __syncthreads();
        buf ^= 1;
    }

    // epilogue: weight-scale rows -> g_y
#pragma unroll
    for (int mf = 0; mf < 2; mf++) {
        const int rbase = row0 + m0 + mf * 16 + g;
        const float w1 = (rbase < n_e)     ? sw[m0 + mf * 16 + g]     : 0.f;
        const float w2 = (rbase + 8 < n_e) ? sw[m0 + mf * 16 + g + 8] : 0.f;
#pragma unroll
        for (int nf = 0; nf < 4; nf++) {
            const int col = col0 + n0 + nf * 8 + 2 * t;
            if (rbase < n_e) {
                float2 o = { w1 * acc[mf][nf][0], w1 * acc[mf][nf][1] };
                *(float2*)(g_y + ((size_t)e * CAP + rbase) * D_DIM + col) = o;
            }
            if (rbase + 8 < n_e) {
                float2 o = { w2 * acc[mf][nf][2], w2 * acc[mf][nf][3] };
                *(float2*)(g_y + ((size_t)e * CAP + rbase + 8) * D_DIM + col) = o;
            }
        }
    }
}

// ---------------- kernel 4: combine (gather-sum per token) ------------------
__global__ __launch_bounds__(192) void combine_kernel(float* __restrict__ out)
{
    const int tk = blockIdx.x;
    const int tid = threadIdx.x;
    __shared__ int slots[TOPK];
    if (tid < TOPK) slots[tid] = g_tok_slot[tk * TOPK + tid];
    __syncthreads();

    float4 a0 = make_float4(0.f, 0.f, 0.f, 0.f);
    float4 a1 = a0;
#pragma unroll
    for (int k = 0; k < TOPK; k++) {
        const int s = slots[k];
        if (s < 0) continue;
        const float4* row = (const float4*)(g_y + (size_t)s * D_DIM);
        float4 v0 = row[tid * 2], v1 = row[tid * 2 + 1];
        a0.x += v0.x; a0.y += v0.y; a0.z += v0.z; a0.w += v0.w;
        a1.x += v1.x; a1.y += v1.y; a1.z += v1.z; a1.w += v1.w;
    }
    float4* o = (float4*)(out + (size_t)tk * D_DIM);
    o[tid * 2] = a0;
    o[tid * 2 + 1] = a1;
}

// ---------------- launcher --------------------------------------------------
extern "C" void kernel_launch(void* const* d_in, const int* in_sizes, int n_in,
                              void* d_out, int out_size)
{
    const float* x      = (const float*)d_in[0];
    const float* gate_w = (const float*)d_in[1];
    const float* W_gate = (const float*)d_in[2];
    const float* W_up   = (const float*)d_in[3];
    const float* W_down = (const float*)d_in[4];
    float* out = (float*)d_out;

    const int router_smem = 8 * D_DIM * 4 + 8 * E_NUM * 4;  // 51200
    cudaFuncSetAttribute(router_kernel,
                         cudaFuncAttributeMaxDynamicSharedMemorySize, router_smem);

    init_kernel<<<1, 64>>>();
    router_kernel<<<T_NUM / 8, 256, router_smem>>>(x, gate_w);
    gemm1_kernel<<<dim3(CAP / 128, H_DIM / 64, E_NUM), 256>>>(x, W_gate, W_up);
    gemm2_kernel<<<dim3(CAP / 128, D_DIM / 64, E_NUM), 256>>>(W_down);
    combine_kernel<<<T_NUM, 192>>>(out);
}